// round 3
// baseline (speedup 1.0000x reference)
#include <cuda_runtime.h>

// PosMLP split into: (A) generator GEMM -> scratch, (B) grid evaluation.
// Eval identity: relu(t) = (t+|t|)/2, t_k = ty_k[h] + tx_k[w]
//   out = P + Qy*rel_y[h] + Qx*rel_x[w] + sum_k |t_k| * (w2_k/2)
// with P = b2 + 0.5*sum b1*w2, Qy = 0.5*sum w1y*w2, Qx = 0.5*sum w1x*w2.
// Inner loop uses packed f32x2 add/fma; abs via 64-bit sign mask (alu pipe).

constexpr int C_DIM = 256;
constexpr int HD    = 16;
constexpr int NW    = 4*HD + 1;   // 65
constexpr int GH    = 48;
constexpr int GW    = 48;
constexpr int W_STR = 72;         // padded stride for per-query weights
constexpr int MAXQ  = 4096;

__device__ float g_wbuf[MAXQ * W_STR];   // scratch: generated weights per query

// ---------------- packed f32x2 helpers ----------------
__device__ __forceinline__ unsigned long long packf2(float lo, float hi) {
    unsigned long long r;
    asm("mov.b64 %0, {%1, %2};" : "=l"(r) : "f"(lo), "f"(hi));
    return r;
}
__device__ __forceinline__ void unpackf2(float& lo, float& hi, unsigned long long v) {
    asm("mov.b64 {%0, %1}, %2;" : "=f"(lo), "=f"(hi) : "l"(v));
}
__device__ __forceinline__ unsigned long long add2(unsigned long long a, unsigned long long b) {
    unsigned long long d;
    asm("add.rn.f32x2 %0, %1, %2;" : "=l"(d) : "l"(a), "l"(b));
    return d;
}
__device__ __forceinline__ unsigned long long fma2(unsigned long long a, unsigned long long b,
                                                   unsigned long long c) {
    unsigned long long d;
    asm("fma.rn.f32x2 %0, %1, %2, %3;" : "=l"(d) : "l"(a), "l"(b), "l"(c));
    return d;
}
constexpr unsigned long long ABS2_MASK = 0x7FFFFFFF7FFFFFFFULL;

// ---------------- Kernel A: weights[q][n] = dot(queries[q], w_gen[n]) + b_gen[n] ----------------
constexpr int QPB = 8;    // queries per block, one warp each
__global__ __launch_bounds__(256)
void posmlp_gen(const float* __restrict__ queries,
                const float* __restrict__ w_gen,
                const float* __restrict__ b_gen,
                int BQ)
{
    __shared__ __align__(16) float s_q[QPB][C_DIM];
    const int tid  = threadIdx.x;
    const int warp = tid >> 5;
    const int lane = tid & 31;
    const int q0   = blockIdx.x * QPB;

    const int nq = min(QPB, BQ - q0);
    const float4* src = reinterpret_cast<const float4*>(queries + (size_t)q0 * C_DIM);
    for (int i = tid; i < nq * (C_DIM/4); i += 256)
        reinterpret_cast<float4*>(&s_q[0][0])[i] = src[i];
    __syncthreads();

    const int qi = q0 + warp;
    if (qi < BQ) {
        const float4* q4 = reinterpret_cast<const float4*>(s_q[warp]);
        float4 qa = q4[lane * 2];
        float4 qb = q4[lane * 2 + 1];
        for (int n = 0; n < NW; ++n) {
            const float4* w4 = reinterpret_cast<const float4*>(w_gen + n * C_DIM);
            float4 wa = w4[lane * 2];
            float4 wb = w4[lane * 2 + 1];
            float s = 0.f;
            s = fmaf(wa.x, qa.x, s); s = fmaf(wa.y, qa.y, s);
            s = fmaf(wa.z, qa.z, s); s = fmaf(wa.w, qa.w, s);
            s = fmaf(wb.x, qb.x, s); s = fmaf(wb.y, qb.y, s);
            s = fmaf(wb.z, qb.z, s); s = fmaf(wb.w, qb.w, s);
            #pragma unroll
            for (int off = 16; off; off >>= 1)
                s += __shfl_xor_sync(0xffffffffu, s, off);
            if (lane == 0) g_wbuf[(size_t)qi * W_STR + n] = s + b_gen[n];
        }
    }
}

// ---------------- Kernel B: evaluate 48x48 grid per query ----------------
constexpr int TPB_B = 96;   // 3 warps; thread tile = 2 rows x 12 cols

__global__ __launch_bounds__(TPB_B)
void posmlp_eval(const float* __restrict__ pos,
                 float* __restrict__ out)
{
    __shared__ float s_w[NW];
    __shared__ __align__(16) float s_ty[HD][GH];
    __shared__ __align__(16) float s_tx[HD][GW];
    __shared__ __align__(16) float s_sy[GH];     // Qy * rel_y[h]
    __shared__ __align__(16) float s_sxb[GW];    // Qx * rel_x[w] + P (P includes b2)
    __shared__ __align__(16) unsigned long long s_w2p[HD];  // packed (w2/2, w2/2)
    __shared__ float s_red[3];                   // Qy, Qx, P

    const int bq  = blockIdx.x;
    const int tid = threadIdx.x;

    if (tid < NW) s_w[tid] = g_wbuf[(size_t)bq * W_STR + tid];
    __syncthreads();

    const float cx = pos[bq*4 + 0];
    const float cy = pos[bq*4 + 1];
    const float inv_bw = 1.0f / pos[bq*4 + 2];
    const float inv_bh = 1.0f / pos[bq*4 + 3];

    // separable tables ty/tx
    #pragma unroll
    for (int it = 0; it < (HD*GH)/TPB_B; ++it) {
        int i = tid + it * TPB_B;
        int k = i / GH, g = i % GH;
        float gc    = ((float)g + 0.5f) * (1.0f / (float)GH);
        float rel_y = (gc - cy) * inv_bh;
        float rel_x = (gc - cx) * inv_bw;
        s_ty[k][g] = fmaf(rel_y, s_w[2*k], s_w[2*HD + k]);
        s_tx[k][g] = rel_x * s_w[2*k + 1];
    }
    // scalar reductions (linear part coefficients)
    if (tid < 3) {
        float s = 0.f;
        #pragma unroll
        for (int k = 0; k < HD; ++k) {
            float w2 = s_w[3*HD + k];
            float v  = (tid == 0) ? s_w[2*k] : (tid == 1) ? s_w[2*k + 1] : s_w[2*HD + k];
            s = fmaf(v, w2, s);
        }
        s *= 0.5f;
        if (tid == 2) s += s_w[4*HD];   // P includes b2
        s_red[tid] = s;
    }
    if (tid < HD) {
        float w2h = 0.5f * s_w[3*HD + tid];
        s_w2p[tid] = packf2(w2h, w2h);
    }
    __syncthreads();

    // tiny base tables
    if (tid < 2 * GH) {
        const bool isX = (tid >= GH);
        const int  g   = isX ? tid - GH : tid;
        float gc = ((float)g + 0.5f) * (1.0f / (float)GH);
        if (isX) s_sxb[g] = fmaf((gc - cx) * inv_bw, s_red[1], s_red[2]);
        else     s_sy[g]  = (gc - cy) * inv_bh * s_red[0];
    }
    __syncthreads();

    // ---- main loop: 2 rows x 12 cols per thread ----
    const int h0 = (tid >> 2) * 2;        // 0..46 even
    const int w0 = (tid & 3) * 12;        // 0,12,24,36

    unsigned long long accA[6], accB[6];
    #pragma unroll
    for (int p = 0; p < 6; ++p) { accA[p] = 0ull; accB[p] = 0ull; }

    #pragma unroll
    for (int k = 0; k < HD; ++k) {
        float2 typ = *reinterpret_cast<const float2*>(&s_ty[k][h0]);  // LDS.64
        unsigned long long ty2a = packf2(typ.x, typ.x);
        unsigned long long ty2b = packf2(typ.y, typ.y);
        unsigned long long w2p  = s_w2p[k];                            // broadcast

        float4 t0 = *reinterpret_cast<const float4*>(&s_tx[k][w0]);
        float4 t1 = *reinterpret_cast<const float4*>(&s_tx[k][w0 + 4]);
        float4 t2 = *reinterpret_cast<const float4*>(&s_tx[k][w0 + 8]);
        unsigned long long txp[6];
        txp[0] = packf2(t0.x, t0.y); txp[1] = packf2(t0.z, t0.w);
        txp[2] = packf2(t1.x, t1.y); txp[3] = packf2(t1.z, t1.w);
        txp[4] = packf2(t2.x, t2.y); txp[5] = packf2(t2.z, t2.w);

        #pragma unroll
        for (int p = 0; p < 6; ++p) {
            unsigned long long ta = add2(ty2a, txp[p]) & ABS2_MASK;
            unsigned long long tb = add2(ty2b, txp[p]) & ABS2_MASK;
            accA[p] = fma2(ta, w2p, accA[p]);
            accB[p] = fma2(tb, w2p, accB[p]);
        }
    }

    // ---- epilogue: add separable base, store 2 rows x 12 floats ----
    float sxb[12];
    #pragma unroll
    for (int j = 0; j < 3; ++j) {
        float4 v = *reinterpret_cast<const float4*>(&s_sxb[w0 + 4*j]);
        sxb[4*j+0] = v.x; sxb[4*j+1] = v.y; sxb[4*j+2] = v.z; sxb[4*j+3] = v.w;
    }
    float syA = s_sy[h0];
    float syB = s_sy[h0 + 1];

    float* outp = out + (size_t)bq * (GH * GW);
    float rowA[12], rowB[12];
    #pragma unroll
    for (int p = 0; p < 6; ++p) {
        float aLo, aHi, bLo, bHi;
        unpackf2(aLo, aHi, accA[p]);
        unpackf2(bLo, bHi, accB[p]);
        rowA[2*p]   = aLo + (syA + sxb[2*p]);
        rowA[2*p+1] = aHi + (syA + sxb[2*p+1]);
        rowB[2*p]   = bLo + (syB + sxb[2*p]);
        rowB[2*p+1] = bHi + (syB + sxb[2*p+1]);
    }
    #pragma unroll
    for (int j = 0; j < 3; ++j) {
        float4 ra, rb;
        ra.x = rowA[4*j]; ra.y = rowA[4*j+1]; ra.z = rowA[4*j+2]; ra.w = rowA[4*j+3];
        rb.x = rowB[4*j]; rb.y = rowB[4*j+1]; rb.z = rowB[4*j+2]; rb.w = rowB[4*j+3];
        *reinterpret_cast<float4*>(&outp[ h0      * GW + w0 + 4*j]) = ra;
        *reinterpret_cast<float4*>(&outp[(h0 + 1) * GW + w0 + 4*j]) = rb;
    }
}

extern "C" void kernel_launch(void* const* d_in, const int* in_sizes, int n_in,
                              void* d_out, int out_size)
{
    const float* queries = (const float*)d_in[0];
    const float* pos     = (const float*)d_in[1];
    const float* w_gen   = (const float*)d_in[2];
    const float* b_gen   = (const float*)d_in[3];
    float* out = (float*)d_out;

    int BQ = in_sizes[0] / C_DIM;   // 1800
    posmlp_gen<<<(BQ + QPB - 1) / QPB, 256>>>(queries, w_gen, b_gen, BQ);
    posmlp_eval<<<BQ, TPB_B>>>(pos, out);
}

// round 5
// speedup vs baseline: 1.9257x; 1.9257x over previous
#include <cuda_runtime.h>

// PosMLP split: (A) generator GEMM -> g_wbuf scratch, (B) grid evaluation.
// Eval identity: relu(t) = (t+|t|)/2, t_k = ty_k[h] + tx_k[w]
//   out = P + Qy*rel_y[h] + Qx*rel_x[w] + sum_k |t_k| * (w2_k/2)
// Inner loop: packed f32x2 add/fma; abs via 64-bit sign mask (alu pipe).

constexpr int C_DIM = 256;
constexpr int HD    = 16;
constexpr int NW    = 4*HD + 1;   // 65
constexpr int GH    = 48;
constexpr int GW    = 48;
constexpr int W_STR = 72;         // padded stride for per-query weights
constexpr int MAXQ  = 4096;

__device__ float g_wbuf[MAXQ * W_STR];

// ---------------- packed f32x2 helpers ----------------
__device__ __forceinline__ unsigned long long packf2(float lo, float hi) {
    unsigned long long r;
    asm("mov.b64 %0, {%1, %2};" : "=l"(r) : "f"(lo), "f"(hi));
    return r;
}
__device__ __forceinline__ void unpackf2(float& lo, float& hi, unsigned long long v) {
    asm("mov.b64 {%0, %1}, %2;" : "=f"(lo), "=f"(hi) : "l"(v));
}
__device__ __forceinline__ unsigned long long add2(unsigned long long a, unsigned long long b) {
    unsigned long long d;
    asm("add.rn.f32x2 %0, %1, %2;" : "=l"(d) : "l"(a), "l"(b));
    return d;
}
__device__ __forceinline__ unsigned long long fma2(unsigned long long a, unsigned long long b,
                                                   unsigned long long c) {
    unsigned long long d;
    asm("fma.rn.f32x2 %0, %1, %2, %3;" : "=l"(d) : "l"(a), "l"(b), "l"(c));
    return d;
}
constexpr unsigned long long ABS2_MASK = 0x7FFFFFFF7FFFFFFFULL;

// ---------------- Kernel A: reduction-free tiled GEMM ----------------
// weights[q][n] = dot(queries[q], w_gen[n]) + b_gen[n]
// Block: 256 threads, QT=16 queries, all 65 n. Thread (q = tid&15, g = tid>>4)
// computes n in {g, g+16, g+32, g+48} (+ n=64 when g==0). K chunked by 64.
constexpr int QT   = 16;
constexpr int KC   = 64;
constexpr int QSTR = 260;   // s_q float stride
constexpr int WSTR = 68;    // s_wg float stride

__global__ __launch_bounds__(256)
void posmlp_gen(const float* __restrict__ queries,
                const float* __restrict__ w_gen,
                const float* __restrict__ b_gen,
                int BQ)
{
    __shared__ __align__(16) float s_q[QT][QSTR];
    __shared__ __align__(16) float s_wg[NW][WSTR];

    const int tid = threadIdx.x;
    const int q0  = blockIdx.x * QT;
    const int nq  = min(QT, BQ - q0);

    // stage full query rows (16 x 256 floats), coalesced float4
    for (int i = tid; i < nq * (C_DIM/4); i += 256) {
        int q = i >> 6, c = i & 63;
        float4 v = reinterpret_cast<const float4*>(queries + (size_t)(q0 + q) * C_DIM)[c];
        *reinterpret_cast<float4*>(&s_q[q][c * 4]) = v;
    }

    const int q  = tid & 15;
    const int g  = tid >> 4;
    const int NJ = (g == 0) ? 5 : 4;

    float acc[5] = {0.f, 0.f, 0.f, 0.f, 0.f};

    #pragma unroll
    for (int c = 0; c < C_DIM / KC; ++c) {
        __syncthreads();   // previous chunk consumed (also orders s_q writes before c=0 compute via the next sync)
        // stage W chunk: 65 rows x 64 cols
        for (int i = tid; i < NW * (KC/4); i += 256) {
            int n = i >> 4, col = i & 15;
            float4 v = *reinterpret_cast<const float4*>(w_gen + n * C_DIM + c * KC + col * 4);
            *reinterpret_cast<float4*>(&s_wg[n][col * 4]) = v;
        }
        __syncthreads();

        #pragma unroll
        for (int kk = 0; kk < KC/4; ++kk) {
            float4 qv = *reinterpret_cast<const float4*>(&s_q[q][c * KC + kk * 4]);
            #pragma unroll
            for (int j = 0; j < 5; ++j) {
                if (j < NJ) {
                    int n = g + 16 * j;            // j==4 only when g==0 -> n=64
                    float4 wv = *reinterpret_cast<const float4*>(&s_wg[n][kk * 4]);
                    acc[j] = fmaf(qv.x, wv.x,
                             fmaf(qv.y, wv.y,
                             fmaf(qv.z, wv.z,
                             fmaf(qv.w, wv.w, acc[j]))));
                }
            }
        }
    }

    if (q < nq) {
        #pragma unroll
        for (int j = 0; j < 5; ++j) {
            if (j < NJ) {
                int n = g + 16 * j;
                g_wbuf[(size_t)(q0 + q) * W_STR + n] = acc[j] + b_gen[n];
            }
        }
    }
}

// ---------------- Kernel B: evaluate 48x48 grid per query ----------------
constexpr int TPB_B = 96;   // 3 warps; thread tile = 2 rows x 12 cols

__global__ __launch_bounds__(TPB_B)
void posmlp_eval(const float* __restrict__ pos,
                 float* __restrict__ out)
{
    __shared__ float s_w[NW];
    __shared__ __align__(16) float s_ty[HD][GH];
    __shared__ __align__(16) float s_tx[HD][GW];
    __shared__ __align__(16) float s_sy[GH];     // Qy * rel_y[h]
    __shared__ __align__(16) float s_sxb[GW];    // Qx * rel_x[w] + P
    __shared__ __align__(16) unsigned long long s_w2p[HD];  // packed (w2/2, w2/2)
    __shared__ float s_red[3];                   // Qy, Qx, P

    const int bq  = blockIdx.x;
    const int tid = threadIdx.x;

    if (tid < NW) s_w[tid] = g_wbuf[(size_t)bq * W_STR + tid];
    __syncthreads();

    const float cx = pos[bq*4 + 0];
    const float cy = pos[bq*4 + 1];
    const float inv_bw = 1.0f / pos[bq*4 + 2];
    const float inv_bh = 1.0f / pos[bq*4 + 3];

    #pragma unroll
    for (int it = 0; it < (HD*GH)/TPB_B; ++it) {
        int i = tid + it * TPB_B;
        int k = i / GH, g = i % GH;
        float gc    = ((float)g + 0.5f) * (1.0f / (float)GH);
        float rel_y = (gc - cy) * inv_bh;
        float rel_x = (gc - cx) * inv_bw;
        s_ty[k][g] = fmaf(rel_y, s_w[2*k], s_w[2*HD + k]);
        s_tx[k][g] = rel_x * s_w[2*k + 1];
    }
    if (tid < 3) {
        float s = 0.f;
        #pragma unroll
        for (int k = 0; k < HD; ++k) {
            float w2 = s_w[3*HD + k];
            float v  = (tid == 0) ? s_w[2*k] : (tid == 1) ? s_w[2*k + 1] : s_w[2*HD + k];
            s = fmaf(v, w2, s);
        }
        s *= 0.5f;
        if (tid == 2) s += s_w[4*HD];
        s_red[tid] = s;
    }
    if (tid < HD) {
        float w2h = 0.5f * s_w[3*HD + tid];
        s_w2p[tid] = packf2(w2h, w2h);
    }
    __syncthreads();

    if (tid < 2 * GH) {
        const bool isX = (tid >= GH);
        const int  g   = isX ? tid - GH : tid;
        float gc = ((float)g + 0.5f) * (1.0f / (float)GH);
        if (isX) s_sxb[g] = fmaf((gc - cx) * inv_bw, s_red[1], s_red[2]);
        else     s_sy[g]  = (gc - cy) * inv_bh * s_red[0];
    }
    __syncthreads();

    // ---- main loop: 2 rows x 12 cols per thread ----
    const int h0 = (tid >> 2) * 2;        // 0..46 even
    const int w0 = (tid & 3) * 12;        // 0,12,24,36  (48B-aligned)

    unsigned long long accA[6], accB[6];
    #pragma unroll
    for (int p = 0; p < 6; ++p) { accA[p] = 0ull; accB[p] = 0ull; }

    #pragma unroll
    for (int k = 0; k < HD; ++k) {
        float2 typ = *reinterpret_cast<const float2*>(&s_ty[k][h0]);  // LDS.64
        unsigned long long ty2a = packf2(typ.x, typ.x);
        unsigned long long ty2b = packf2(typ.y, typ.y);
        unsigned long long w2p  = s_w2p[k];                            // broadcast LDS

        // tx: 3 x LDS.128, each ulonglong2 = two ready-made f32x2 operands (no MOVs)
        const ulonglong2* txv = reinterpret_cast<const ulonglong2*>(&s_tx[k][w0]);
        ulonglong2 u0 = txv[0];
        ulonglong2 u1 = txv[1];
        ulonglong2 u2 = txv[2];
        unsigned long long txp[6] = {u0.x, u0.y, u1.x, u1.y, u2.x, u2.y};

        #pragma unroll
        for (int p = 0; p < 6; ++p) {
            unsigned long long ta = add2(ty2a, txp[p]) & ABS2_MASK;
            unsigned long long tb = add2(ty2b, txp[p]) & ABS2_MASK;
            accA[p] = fma2(ta, w2p, accA[p]);
            accB[p] = fma2(tb, w2p, accB[p]);
        }
    }

    // ---- epilogue ----
    float sxb[12];
    #pragma unroll
    for (int j = 0; j < 3; ++j) {
        float4 v = *reinterpret_cast<const float4*>(&s_sxb[w0 + 4*j]);
        sxb[4*j+0] = v.x; sxb[4*j+1] = v.y; sxb[4*j+2] = v.z; sxb[4*j+3] = v.w;
    }
    float syA = s_sy[h0];
    float syB = s_sy[h0 + 1];

    float* outp = out + (size_t)bq * (GH * GW);
    float rowA[12], rowB[12];
    #pragma unroll
    for (int p = 0; p < 6; ++p) {
        float aLo, aHi, bLo, bHi;
        unpackf2(aLo, aHi, accA[p]);
        unpackf2(bLo, bHi, accB[p]);
        rowA[2*p]   = aLo + (syA + sxb[2*p]);
        rowA[2*p+1] = aHi + (syA + sxb[2*p+1]);
        rowB[2*p]   = bLo + (syB + sxb[2*p]);
        rowB[2*p+1] = bHi + (syB + sxb[2*p+1]);
    }
    #pragma unroll
    for (int j = 0; j < 3; ++j) {
        float4 ra, rb;
        ra.x = rowA[4*j]; ra.y = rowA[4*j+1]; ra.z = rowA[4*j+2]; ra.w = rowA[4*j+3];
        rb.x = rowB[4*j]; rb.y = rowB[4*j+1]; rb.z = rowB[4*j+2]; rb.w = rowB[4*j+3];
        *reinterpret_cast<float4*>(&outp[ h0      * GW + w0 + 4*j]) = ra;
        *reinterpret_cast<float4*>(&outp[(h0 + 1) * GW + w0 + 4*j]) = rb;
    }
}

extern "C" void kernel_launch(void* const* d_in, const int* in_sizes, int n_in,
                              void* d_out, int out_size)
{
    const float* queries = (const float*)d_in[0];
    const float* pos     = (const float*)d_in[1];
    const float* w_gen   = (const float*)d_in[2];
    const float* b_gen   = (const float*)d_in[3];
    float* out = (float*)d_out;

    int BQ = in_sizes[0] / C_DIM;   // 1800
    posmlp_gen<<<(BQ + QT - 1) / QT, 256>>>(queries, w_gen, b_gen, BQ);
    posmlp_eval<<<BQ, TPB_B>>>(pos, out);
}